// round 4
// baseline (speedup 1.0000x reference)
#include <cuda_runtime.h>
#include <cuda_bf16.h>
#include <cstdint>

#define SS 2048
#define BB 64
#define DD 512

// ---------------- device scratch (static; no runtime allocs) ----------------
__device__ float g_u[BB * DD];                          // u[b,a] = input.W1x + b1
__device__ __align__(16) __nv_bfloat16 g_whi[DD * DD];  // W1_src hi, K-major [a][d]
__device__ __align__(16) __nv_bfloat16 g_wlo[DD * DD];  // W1_src lo
__device__ float g_part[4 * BB * DD];                   // ctx partials

// ---------------- helpers ----------------
__device__ __forceinline__ uint32_t smem_u32(const void* p) {
    uint32_t a;
    asm("{ .reg .u64 t; cvta.to.shared.u64 t, %1; cvt.u32.u64 %0, t; }" : "=r"(a) : "l"(p));
    return a;
}
__device__ __forceinline__ uint32_t pack2(__nv_bfloat16 a, __nv_bfloat16 b) {
    return (uint32_t)__bfloat16_as_ushort(a) | ((uint32_t)__bfloat16_as_ushort(b) << 16);
}
__device__ __forceinline__ void cp16(uint32_t dst, const void* src) {
    asm volatile("cp.async.cg.shared.global [%0], [%1], 16;" :: "r"(dst), "l"(src) : "memory");
}
__device__ __forceinline__ float tanh_f(float x) {
    float e = __expf(2.f * x);
    return 1.f - __fdividef(2.f, e + 1.f);
}

#define LDSM4(r, addr) \
    asm volatile("ldmatrix.sync.aligned.m8n8.x4.shared.b16 {%0,%1,%2,%3}, [%4];" \
        : "=r"((r)[0]), "=r"((r)[1]), "=r"((r)[2]), "=r"((r)[3]) : "r"(addr))

#define MMA(d, a, b) \
    asm volatile("mma.sync.aligned.m16n8k16.row.col.f32.bf16.bf16.f32 " \
        "{%0,%1,%2,%3}, {%4,%5,%6,%7}, {%8,%9}, {%0,%1,%2,%3};" \
        : "+f"((d)[0]), "+f"((d)[1]), "+f"((d)[2]), "+f"((d)[3]) \
        : "r"((a)[0]), "r"((a)[1]), "r"((a)[2]), "r"((a)[3]), "r"((b)[0]), "r"((b)[1]))

// ---------------- smem layout for gemm_k ----------------
#define U_OFF    0
#define W2_OFF   2048
#define RED_OFF  4096
#define TILE_OFF 5120
#define ROWB     80          // padded row stride (64B data + 16B pad) -> conflict-free LDSM
#define AHI_O    0           // 128 rows
#define ALO_O    10240
#define BHI_O    20480       // 128 rows
#define BLO_O    30720
#define ST_SZ    40960
#define DYN_SMEM (TILE_OFF + 2 * ST_SZ)   // 87040

// ==================== prep: u[b,a] and W hi/lo split ====================
__global__ void prep_k(const float* __restrict__ input, const float* __restrict__ W1,
                       const float* __restrict__ b1) {
    __shared__ float inp[DD];
    int blk = blockIdx.x, tid = threadIdx.x;
    if (blk < BB) {
        inp[tid] = input[blk * DD + tid];
        inp[tid + 256] = input[blk * DD + tid + 256];
        __syncthreads();
        for (int a = tid; a < DD; a += 256) {
            const float* w = W1 + (size_t)a * (2 * DD);
            float acc = b1[a];
            #pragma unroll 8
            for (int d = 0; d < DD; d++) acc += inp[d] * w[d];
            g_u[blk * DD + a] = acc;
        }
    } else {
        int base = (blk - BB) * 16384;
        for (int i = tid; i < 16384; i += 256) {
            int idx = base + i;
            int a = idx >> 9, j = idx & 511;
            float v = W1[(size_t)a * (2 * DD) + DD + j];
            __nv_bfloat16 h = __float2bfloat16(v);
            g_whi[idx] = h;
            g_wlo[idx] = __float2bfloat16(v - __bfloat162float(h));
        }
    }
}

// ==================== GEMM (bf16 3-term split) + fused score epilogue ====================
__global__ void __launch_bounds__(256, 1)
gemm_k(const float* __restrict__ src, float* __restrict__ scores, const float* __restrict__ W2) {
    extern __shared__ char sm[];
    uint32_t smb = smem_u32(sm);
    int tid = threadIdx.x, lid = tid & 31, wid = tid >> 5;
    int wm = wid & 3, wn = wid >> 2;     // 4 m-warps x 2 n-warps
    int b = blockIdx.y;
    int s0 = blockIdx.x * 128;

    float* u_sm  = (float*)(sm + U_OFF);
    float* w2_sm = (float*)(sm + W2_OFF);
    for (int i = tid; i < DD; i += 256) { u_sm[i] = g_u[b * DD + i]; w2_sm[i] = W2[i]; }
    __syncthreads();

    const float* srcb = src + (size_t)b * DD;   // src[s][b][d]; s-stride = BB*DD

    // per-thread fixed mappings
    const int a_r  = tid >> 3;            // A rows handled: a_r + {0,32,64,96}? no: q=tid+256t
    const int a_s4 = tid & 7;
    (void)a_r; (void)a_s4;

    float sc[4] = {0.f, 0.f, 0.f, 0.f};  // per-thread row-score partials

    for (int nt = 0; nt < 4; nt++) {
        float acc[2][8][4];
        #pragma unroll
        for (int i = 0; i < 2; i++)
            #pragma unroll
            for (int j = 0; j < 8; j++)
                #pragma unroll
                for (int k = 0; k < 4; k++) acc[i][j][k] = 0.f;

        const __nv_bfloat16* wh = g_whi + (size_t)(nt * 128) * DD;
        const __nv_bfloat16* wl = g_wlo + (size_t)(nt * 128) * DD;

        float4 av[4];
        // ---- prologue: chunk 0 into stage 0 ----
        {
            int k0 = 0;
            #pragma unroll
            for (int t = 0; t < 4; t++) {
                int q = tid + 256 * t, r = q >> 3, s4 = q & 7;
                av[t] = *(const float4*)(srcb + (size_t)(s0 + r) * (BB * DD) + k0 + s4 * 4);
            }
            uint32_t sb = smb + TILE_OFF;
            #pragma unroll
            for (int t = 0; t < 2; t++) {
                int q = tid + 256 * t, n = q >> 2, sg = q & 3;
                uint32_t d0 = sb + (uint32_t)(n * ROWB + sg * 16);
                cp16(d0 + BHI_O, wh + (size_t)n * DD + k0 + sg * 8);
                cp16(d0 + BLO_O, wl + (size_t)n * DD + k0 + sg * 8);
            }
            asm volatile("cp.async.commit_group;" ::: "memory");
            char* sp = sm + TILE_OFF;
            #pragma unroll
            for (int t = 0; t < 4; t++) {
                int q = tid + 256 * t, r = q >> 3, s4 = q & 7;
                float4 v = av[t];
                __nv_bfloat16 h0 = __float2bfloat16(v.x), h1 = __float2bfloat16(v.y);
                __nv_bfloat16 h2 = __float2bfloat16(v.z), h3 = __float2bfloat16(v.w);
                __nv_bfloat16 l0 = __float2bfloat16(v.x - __bfloat162float(h0));
                __nv_bfloat16 l1 = __float2bfloat16(v.y - __bfloat162float(h1));
                __nv_bfloat16 l2 = __float2bfloat16(v.z - __bfloat162float(h2));
                __nv_bfloat16 l3 = __float2bfloat16(v.w - __bfloat162float(h3));
                uint32_t off = (uint32_t)(r * ROWB + s4 * 8);
                *(uint2*)(sp + AHI_O + off) = make_uint2(pack2(h0, h1), pack2(h2, h3));
                *(uint2*)(sp + ALO_O + off) = make_uint2(pack2(l0, l1), pack2(l2, l3));
            }
        }

        for (int ck = 0; ck < 16; ck++) {
            int st = ck & 1;
            uint32_t sbase = smb + TILE_OFF + st * ST_SZ;

            if (ck < 15) {  // prefetch next A into regs (latency hidden under mma)
                int k0 = (ck + 1) * 32;
                #pragma unroll
                for (int t = 0; t < 4; t++) {
                    int q = tid + 256 * t, r = q >> 3, s4 = q & 7;
                    av[t] = *(const float4*)(srcb + (size_t)(s0 + r) * (BB * DD) + k0 + s4 * 4);
                }
            }
            asm volatile("cp.async.wait_group 0;" ::: "memory");
            __syncthreads();
            if (ck < 15) {  // issue next B cp.async into other stage
                int k0 = (ck + 1) * 32;
                uint32_t sb = smb + TILE_OFF + (st ^ 1) * ST_SZ;
                #pragma unroll
                for (int t = 0; t < 2; t++) {
                    int q = tid + 256 * t, n = q >> 2, sg = q & 3;
                    uint32_t d0 = sb + (uint32_t)(n * ROWB + sg * 16);
                    cp16(d0 + BHI_O, wh + (size_t)n * DD + k0 + sg * 8);
                    cp16(d0 + BLO_O, wl + (size_t)n * DD + k0 + sg * 8);
                }
                asm volatile("cp.async.commit_group;" ::: "memory");
            }

            // ---- mma on current stage ----
            #pragma unroll
            for (int ks = 0; ks < 2; ks++) {
                uint32_t ahi[2][4], alo[2][4];
                uint32_t aoff = (uint32_t)((wm * 32 + (lid & 15)) * ROWB) + ks * 32 + (lid >> 4) * 16;
                LDSM4(ahi[0], sbase + AHI_O + aoff);
                LDSM4(ahi[1], sbase + AHI_O + aoff + 16 * ROWB);
                LDSM4(alo[0], sbase + ALO_O + aoff);
                LDSM4(alo[1], sbase + ALO_O + aoff + 16 * ROWB);
                #pragma unroll
                for (int p = 0; p < 4; p++) {
                    uint32_t bh[4], bl[4];
                    uint32_t boff = (uint32_t)((wn * 64 + p * 16 + ((lid >> 4) << 3) + (lid & 7)) * ROWB)
                                  + ks * 32 + ((lid >> 3) & 1) * 16;
                    LDSM4(bh, sbase + BHI_O + boff);
                    LDSM4(bl, sbase + BLO_O + boff);
                    #pragma unroll
                    for (int mt = 0; mt < 2; mt++) {
                        MMA(acc[mt][2 * p],     ahi[mt], bh);
                        MMA(acc[mt][2 * p + 1], ahi[mt], bh + 2);
                        MMA(acc[mt][2 * p],     alo[mt], bh);
                        MMA(acc[mt][2 * p + 1], alo[mt], bh + 2);
                        MMA(acc[mt][2 * p],     ahi[mt], bl);
                        MMA(acc[mt][2 * p + 1], ahi[mt], bl + 2);
                    }
                }
            }

            if (ck < 15) {  // store prefetched A (hi/lo) into other stage
                char* sp = sm + TILE_OFF + (st ^ 1) * ST_SZ;
                #pragma unroll
                for (int t = 0; t < 4; t++) {
                    int q = tid + 256 * t, r = q >> 3, s4 = q & 7;
                    float4 v = av[t];
                    __nv_bfloat16 h0 = __float2bfloat16(v.x), h1 = __float2bfloat16(v.y);
                    __nv_bfloat16 h2 = __float2bfloat16(v.z), h3 = __float2bfloat16(v.w);
                    __nv_bfloat16 l0 = __float2bfloat16(v.x - __bfloat162float(h0));
                    __nv_bfloat16 l1 = __float2bfloat16(v.y - __bfloat162float(h1));
                    __nv_bfloat16 l2 = __float2bfloat16(v.z - __bfloat162float(h2));
                    __nv_bfloat16 l3 = __float2bfloat16(v.w - __bfloat162float(h3));
                    uint32_t off = (uint32_t)(r * ROWB + s4 * 8);
                    *(uint2*)(sp + AHI_O + off) = make_uint2(pack2(h0, h1), pack2(h2, h3));
                    *(uint2*)(sp + ALO_O + off) = make_uint2(pack2(l0, l1), pack2(l2, l3));
                }
            }
        }

        // ---- epilogue for this n-tile: sc += sum_a W2[a]*tanh(acc + u[a]) ----
        {
            int tq = lid & 3;
            float part[4] = {0.f, 0.f, 0.f, 0.f};
            #pragma unroll
            for (int j = 0; j < 8; j++) {
                int a = nt * 128 + wn * 64 + j * 8 + tq * 2;
                float u0 = u_sm[a], u1 = u_sm[a + 1];
                float w0 = w2_sm[a], w1 = w2_sm[a + 1];
                #pragma unroll
                for (int mt = 0; mt < 2; mt++) {
                    part[mt * 2 + 0] += w0 * tanh_f(acc[mt][j][0] + u0)
                                      + w1 * tanh_f(acc[mt][j][1] + u1);
                    part[mt * 2 + 1] += w0 * tanh_f(acc[mt][j][2] + u0)
                                      + w1 * tanh_f(acc[mt][j][3] + u1);
                }
            }
            #pragma unroll
            for (int i = 0; i < 4; i++) {
                part[i] += __shfl_xor_sync(0xffffffffu, part[i], 1);
                part[i] += __shfl_xor_sync(0xffffffffu, part[i], 2);
                sc[i] += part[i];
            }
        }
    }

    // ---- cross-warp (n-warp) reduction + store scores ----
    float* red = (float*)(sm + RED_OFF);
    __syncthreads();
    if ((lid & 3) == 0) {
        int g = lid >> 2;
        #pragma unroll
        for (int mt = 0; mt < 2; mt++) {
            red[wn * 128 + wm * 32 + mt * 16 + g]     = sc[mt * 2 + 0];
            red[wn * 128 + wm * 32 + mt * 16 + 8 + g] = sc[mt * 2 + 1];
        }
    }
    __syncthreads();
    if (tid < 128)
        scores[(size_t)(s0 + tid) * BB + b] = red[tid] + red[128 + tid];
}

// ==================== softmax over S (in place) ====================
__global__ void softmax_k(float* __restrict__ attn, const unsigned char* __restrict__ mask) {
    __shared__ float red[256];
    int b = blockIdx.x, tid = threadIdx.x;
    float v[8];
    float mx = -1e30f;
    #pragma unroll
    for (int i = 0; i < 8; i++) {
        int s = tid + i * 256;
        float x = attn[(size_t)s * BB + b];
        if (mask[(size_t)s * BB + b]) x = -1e30f;
        v[i] = x;
        mx = fmaxf(mx, x);
    }
    red[tid] = mx; __syncthreads();
    for (int o = 128; o > 0; o >>= 1) { if (tid < o) red[tid] = fmaxf(red[tid], red[tid + o]); __syncthreads(); }
    mx = red[0]; __syncthreads();
    float sum = 0.f;
    #pragma unroll
    for (int i = 0; i < 8; i++) { v[i] = __expf(v[i] - mx); sum += v[i]; }
    red[tid] = sum; __syncthreads();
    for (int o = 128; o > 0; o >>= 1) { if (tid < o) red[tid] += red[tid + o]; __syncthreads(); }
    float inv = __fdividef(1.f, red[0]);
    #pragma unroll
    for (int i = 0; i < 8; i++) attn[(size_t)(tid + i * 256) * BB + b] = v[i] * inv;
}

// ==================== ctx = sum_s attn[s,b] * src[s,b,:] ====================
__global__ void ctx_k(const float* __restrict__ src, const float* __restrict__ attn) {
    int b = blockIdx.x, dch = blockIdx.y, sch = blockIdx.z, tid = threadIdx.x;
    int d = dch * 128 + tid;
    const float* sp = src + (size_t)b * DD + d;
    int s0 = sch * 512;
    float a0 = 0.f, a1 = 0.f, a2 = 0.f, a3 = 0.f;
    for (int s = s0; s < s0 + 512; s += 4) {
        a0 += attn[(size_t)(s + 0) * BB + b] * sp[(size_t)(s + 0) * (BB * DD)];
        a1 += attn[(size_t)(s + 1) * BB + b] * sp[(size_t)(s + 1) * (BB * DD)];
        a2 += attn[(size_t)(s + 2) * BB + b] * sp[(size_t)(s + 2) * (BB * DD)];
        a3 += attn[(size_t)(s + 3) * BB + b] * sp[(size_t)(s + 3) * (BB * DD)];
    }
    g_part[((sch * BB + b) << 9) + d] = (a0 + a1) + (a2 + a3);
}

__global__ void red_k(float* __restrict__ out) {
    int i = blockIdx.x * 512 + threadIdx.x;
    out[i] = (g_part[i] + g_part[32768 + i]) + (g_part[65536 + i] + g_part[98304 + i]);
}

// ==================== launch ====================
extern "C" void kernel_launch(void* const* d_in, const int* in_sizes, int n_in,
                              void* d_out, int out_size) {
    (void)in_sizes; (void)n_in; (void)out_size;
    const float* input = (const float*)d_in[0];
    const float* src = (const float*)d_in[1];
    const unsigned char* mask = (const unsigned char*)d_in[2];
    const float* W1 = (const float*)d_in[3];
    const float* b1 = (const float*)d_in[4];
    const float* W2 = (const float*)d_in[5];
    float* out = (float*)d_out;          // [ctx: 64*512][attn: 2048*64]
    float* attn = out + BB * DD;

    cudaFuncSetAttribute(gemm_k, cudaFuncAttributeMaxDynamicSharedMemorySize, DYN_SMEM);

    prep_k<<<80, 256>>>(input, W1, b1);
    gemm_k<<<dim3(16, BB), 256, DYN_SMEM>>>(src, attn, W2);
    softmax_k<<<BB, 256>>>(attn, mask);
    ctx_k<<<dim3(BB, 4, 4), 128>>>(src, attn);
    red_k<<<BB, 512>>>(out);
}